// round 12
// baseline (speedup 1.0000x reference)
#include <cuda_runtime.h>
#include <cuda_fp16.h>
#include <cstdint>
#include <math.h>

// Problem constants
static constexpr int N = 512;      // batch
static constexpr int D = 512;      // features
static constexpr int C = 50000;    // classes
static constexpr float SCALE = 30.0f;
static constexpr float COS_M = 0.8775825618903728f;   // cos(0.5)
static constexpr float SIN_M = 0.479425538604203f;    // sin(0.5)
static constexpr float TH    = -0.8775825618903728f;  // cos(pi-0.5)
static constexpr float MMC   = 0.2397127693021015f;   // sin(pi-0.5)*0.5

// Device scratch (no runtime allocation allowed)
__device__ __half g_xn[(size_t)N * D];       // normalized x, fp16
__device__ __half g_wn[(size_t)C * D];       // normalized W, fp16  (51.2 MB)
__device__ float  g_rowsum[N];               // sum exp(logit - 30) per row
__device__ float  g_picked[N];               // post-margin scaled logit at label
// Fallback scratch if out_size < N*C (not expected):
__device__ float  g_out_full[(size_t)N * C];

// ---------------------------------------------------------------------------
__device__ __forceinline__ uint32_t smem_u32(const void* p) {
    uint32_t a;
    asm("{ .reg .u64 t; cvta.to.shared.u64 t, %1; cvt.u32.u64 %0, t; }" : "=r"(a) : "l"(p));
    return a;
}
#define CP_ASYNC16(dst, src) \
    asm volatile("cp.async.cg.shared.global [%0], [%1], 16;" :: "r"(dst), "l"(src) : "memory")
#define CP_ASYNC16_ZF(dst, src, srcsz) \
    asm volatile("cp.async.cg.shared.global [%0], [%1], 16, %2;" :: "r"(dst), "l"(src), "r"(srcsz) : "memory")
#define CP_COMMIT() asm volatile("cp.async.commit_group;" ::: "memory")
#define CP_WAIT(n)  asm volatile("cp.async.wait_group %0;" :: "n"(n) : "memory")

#define LDSM_X4(r0, r1, r2, r3, addr) \
    asm volatile("ldmatrix.sync.aligned.m8n8.x4.shared.b16 {%0,%1,%2,%3}, [%4];" \
        : "=r"(r0), "=r"(r1), "=r"(r2), "=r"(r3) : "r"(addr))

#define MMA16816(d, a, b0_, b1_) \
    asm volatile("mma.sync.aligned.m16n8k16.row.col.f32.f16.f16.f32 " \
        "{%0,%1,%2,%3},{%4,%5,%6,%7},{%8,%9},{%0,%1,%2,%3};" \
        : "+f"((d).x), "+f"((d).y), "+f"((d).z), "+f"((d).w) \
        : "r"((a)[0]), "r"((a)[1]), "r"((a)[2]), "r"((a)[3]), "r"(b0_), "r"(b1_))

// ---------------------------------------------------------------------------
// Row L2-normalize (fp32 in -> fp16 out). Warp per row, 8 rows per block.
// which==0 also zeroes g_rowsum (block 0).
// ---------------------------------------------------------------------------
__global__ void norm_rows_kernel(const float* __restrict__ in, int which)
{
    if (which == 0 && blockIdx.x == 0) {
        g_rowsum[threadIdx.x]       = 0.0f;
        g_rowsum[threadIdx.x + 256] = 0.0f;
    }
    const int warp = threadIdx.x >> 5;
    const int lane = threadIdx.x & 31;
    const int r = blockIdx.x * 8 + warp;
    const float4* rp = reinterpret_cast<const float4*>(in + (size_t)r * D);
    float4 v[4];
    float ss = 0.0f;
    #pragma unroll
    for (int i = 0; i < 4; i++) {
        v[i] = rp[lane + 32 * i];
        ss += v[i].x * v[i].x + v[i].y * v[i].y + v[i].z * v[i].z + v[i].w * v[i].w;
    }
    #pragma unroll
    for (int o = 16; o; o >>= 1) ss += __shfl_xor_sync(0xFFFFFFFFu, ss, o);
    float inv = 1.0f / fmaxf(sqrtf(ss), 1e-12f);
    __half* dst = which ? g_wn : g_xn;
    __half2* op = reinterpret_cast<__half2*>(dst + (size_t)r * D);
    #pragma unroll
    for (int i = 0; i < 4; i++) {
        op[(lane + 32 * i) * 2 + 0] = __floats2half2_rn(v[i].x * inv, v[i].y * inv);
        op[(lane + 32 * i) * 2 + 1] = __floats2half2_rn(v[i].z * inv, v[i].w * inv);
    }
}

// ---------------------------------------------------------------------------
// GEMM: cosine[N, C] = xn[N, D] * wn[C, D]^T  (fp16 in, fp32 acc)
// Block 128x128 with ONLY 4 warps (128 threads, 2x2), warp tile 64x64:
//   - LDSM bytes/MAC = 0.25 (vs 0.375 at 64x32) -> higher smem-side ceiling
//   - small CTA => 2 CTAs/SM, independent pipelines/barriers overlap
// BK=64, 3-stage cp.async pipeline, one sync per K-iter.
// Fused epilogue: phi-margin at label col, x30 scale, per-row exp-sum.
// ---------------------------------------------------------------------------
static constexpr int BM = 128, BN = 128, BK = 64, BKP = 72;  // 144B rows, ldsm conflict-free
static constexpr int ROWB = BKP * 2;                          // 144 bytes per smem row
static constexpr int A_BYTES = BM * ROWB;                     // 18432
static constexpr int B_BYTES = BN * ROWB;                     // 18432
static constexpr int STAGE_BYTES = A_BYTES + B_BYTES;         // 36864
static constexpr int NSTAGE = 3;
static constexpr int KITERS = D / BK;                         // 8
static constexpr int PIPE_BYTES = NSTAGE * STAGE_BYTES;       // 110592
static constexpr int STG_STRIDE = 132;                        // epilogue stage stride (floats)
static constexpr int ROWSUM_OFF = PIPE_BYTES;
static constexpr int LAB_OFF    = ROWSUM_OFF + 128 * (int)sizeof(float);
static constexpr int SMEM_TOTAL = LAB_OFF + 128 * (int)sizeof(int);   // 111616

__global__ void __launch_bounds__(128, 2)
gemm_margin_kernel(const int* __restrict__ labels, float* __restrict__ out)
{
    extern __shared__ __align__(16) unsigned char smraw[];
    const uint32_t smb = smem_u32(smraw);
    float* shRow = reinterpret_cast<float*>(smraw + ROWSUM_OFF);
    int*   shLab = reinterpret_cast<int*>(smraw + LAB_OFF);
    float* stage = reinterpret_cast<float*>(smraw);    // epilogue union (128x132 f32 = 67.6KB)

    const int tid  = threadIdx.x;
    const int warp = tid >> 5;    // 0..3
    const int lane = tid & 31;
    const int wRow = warp >> 1;   // 0..1 (64 rows)
    const int wCol = warp & 1;    // 0..1 (64 cols)
    const int rowBase = blockIdx.x * BM;
    const int colBase = blockIdx.y * BN;

    shRow[tid] = 0.0f;
    shLab[tid] = labels[rowBase + tid];

    float4 acc[4][8];   // [m16 tile i][n8 tile j]  = 128 regs
    #pragma unroll
    for (int i = 0; i < 4; i++)
        #pragma unroll
        for (int j = 0; j < 8; j++)
            acc[i][j] = make_float4(0.f, 0.f, 0.f, 0.f);

    // ldmatrix lane-dependent byte offsets (within a tile's smem region)
    // A: lanes 0-7 rows0-7@k0 | 8-15 rows8-15@k0 | 16-23 rows0-7@k8 | 24-31 rows8-15@k8
    const uint32_t aLane = (uint32_t)((((lane >> 3) & 1) * 8 + (lane & 7)) * ROWB + (lane >> 4) * 16);
    // B: lanes 0-7 n0-7@k0 | 8-15 n0-7@k8 | 16-23 n8-15@k0 | 24-31 n8-15@k8
    const uint32_t bLane = (uint32_t)(((lane >> 4) * 8 + (lane & 7)) * ROWB + ((lane >> 3) & 1) * 16);
    const uint32_t aWarpBase = (uint32_t)(wRow * 64 * ROWB) + aLane;
    const uint32_t bWarpBase = (uint32_t)(A_BYTES + wCol * 64 * ROWB) + bLane;

    // Per-stage loads with 128 threads: A 1024 vec -> 8/thread; B same.
    auto prefetch = [&](int kt) {
        const int slot = kt % NSTAGE;
        const uint32_t sA = smb + slot * STAGE_BYTES;
        const uint32_t sB = sA + A_BYTES;
        #pragma unroll
        for (int j = 0; j < 8; j++) {
            int v   = tid + j * 128;
            int row = v >> 3;
            int cv  = v & 7;
            const __half* asrc = g_xn + (size_t)(rowBase + row) * D + kt * BK + cv * 8;
            CP_ASYNC16(sA + (uint32_t)(row * ROWB + cv * 16), asrc);
        }
        #pragma unroll
        for (int j = 0; j < 8; j++) {
            int v   = tid + j * 128;
            int row = v >> 3;
            int cv  = v & 7;
            int cls = colBase + row;
            const __half* bsrc = g_wn + (size_t)cls * D + kt * BK + cv * 8;
            uint32_t sz = (cls < C) ? 16u : 0u;   // zero-fill OOB class rows
            CP_ASYNC16_ZF(sB + (uint32_t)(row * ROWB + cv * 16), bsrc, sz);
        }
        CP_COMMIT();
    };

    prefetch(0);
    prefetch(1);

    for (int kt = 0; kt < KITERS; kt++) {
        if (kt < KITERS - 1) { CP_WAIT(1); } else { CP_WAIT(0); }
        __syncthreads();

        if (kt + 2 < KITERS) prefetch(kt + 2);

        const uint32_t slotBase = smb + (kt % NSTAGE) * STAGE_BYTES;
        const uint32_t aBase = slotBase + aWarpBase;
        const uint32_t bBase = slotBase + bWarpBase;

        #pragma unroll
        for (int ks = 0; ks < BK / 16; ks++) {
            const uint32_t ko = (uint32_t)(ks * 32);
            uint32_t a[4][4];
            #pragma unroll
            for (int i = 0; i < 4; i++)
                LDSM_X4(a[i][0], a[i][1], a[i][2], a[i][3],
                        aBase + (uint32_t)(i * 16 * ROWB) + ko);
            uint32_t b[4][4];   // group g covers n rows g*16..g*16+15
            #pragma unroll
            for (int g = 0; g < 4; g++)
                LDSM_X4(b[g][0], b[g][1], b[g][2], b[g][3],
                        bBase + (uint32_t)(g * 16 * ROWB) + ko);
            #pragma unroll
            for (int i = 0; i < 4; i++) {
                #pragma unroll
                for (int j = 0; j < 8; j++) {
                    const int g = j >> 1, h = (j & 1) * 2;
                    MMA16816(acc[i][j], a[i], b[g][h], b[g][h + 1]);
                }
            }
        }
    }

    // ------------------ fused epilogue -----------------------------------
    __syncthreads();   // mainloop smem reads done; safe to overwrite with stage
    {
        const int gid = lane >> 2;
        const int c2  = (lane & 3) * 2;
        #pragma unroll
        for (int i = 0; i < 4; i++) {
            const int r0 = wRow * 64 + i * 16 + gid;
            #pragma unroll
            for (int j = 0; j < 8; j++) {
                const int col = wCol * 64 + j * 8 + c2;
                *reinterpret_cast<float2*>(stage + r0 * STG_STRIDE + col) =
                    make_float2(acc[i][j].x, acc[i][j].y);
                *reinterpret_cast<float2*>(stage + (r0 + 8) * STG_STRIDE + col) =
                    make_float2(acc[i][j].z, acc[i][j].w);
            }
        }
    }
    __syncthreads();

    // Warp-per-row processing: 4 warps x 32 iters cover 128 rows.
    #pragma unroll 2
    for (int k = 0; k < 32; k++) {
        const int row = warp + k * 4;             // 0..127, warp-uniform
        const int gr  = rowBase + row;
        const int lab = shLab[row];
        const int gc0 = colBase + lane * 4;
        const float* sp = stage + row * STG_STRIDE + lane * 4;
        float4 v = make_float4(sp[0], sp[1], sp[2], sp[3]);
        float e = 0.0f;
        float* vv = &v.x;
        #pragma unroll
        for (int j = 0; j < 4; j++) {
            float cv = vv[j];
            float val;
            if (gc0 + j == lab) {
                float sine = sqrtf(fmaxf(0.0f, fminf(1.0000001f - cv * cv, 1.0f)));
                float ph   = cv * COS_M - sine * SIN_M;
                val = ((cv > TH) ? ph : (cv - MMC)) * SCALE;
                g_picked[gr] = val;
            } else {
                val = cv * SCALE;
            }
            vv[j] = val;
            e += __expf(val - 30.0f);
        }
        if (gc0 < C) {
            *reinterpret_cast<float4*>(out + (size_t)gr * C + gc0) = v;
        } else {
            e = 0.0f;
        }
        #pragma unroll
        for (int o = 16; o; o >>= 1) e += __shfl_xor_sync(0xFFFFFFFFu, e, o);
        if (lane == 0) atomicAdd(&shRow[row], e);
    }
    __syncthreads();
    atomicAdd(&g_rowsum[rowBase + tid], shRow[tid]);
}

// ---------------------------------------------------------------------------
// Final loss: lse_r = 30 + log(rowsum_r); loss = mean(lse - picked)
// ---------------------------------------------------------------------------
__global__ void finalize_kernel(float* __restrict__ dst)
{
    int tid = threadIdx.x;   // 512 threads
    float v = (30.0f + logf(g_rowsum[tid])) - g_picked[tid];
    #pragma unroll
    for (int o = 16; o; o >>= 1) v += __shfl_xor_sync(0xFFFFFFFFu, v, o);
    __shared__ float sh[16];
    if ((tid & 31) == 0) sh[tid >> 5] = v;
    __syncthreads();
    if (tid == 0) {
        float tot = 0.0f;
        #pragma unroll
        for (int w = 0; w < 16; w++) tot += sh[w];
        dst[0] = tot / (float)N;
    }
}

// ---------------------------------------------------------------------------
extern "C" void kernel_launch(void* const* d_in, const int* in_sizes, int n_in,
                              void* d_out, int out_size)
{
    const float* logits = (const float*)d_in[0];  // [512, 512] f32
    const int*   labels = (const int*)  d_in[1];  // [512] int32
    const float* weight = (const float*)d_in[2];  // [50000, 512] f32

    const long long NC = (long long)N * C;
    float* out;
    float* lossdst = nullptr;
    if ((long long)out_size == NC + 1) {
        out = (float*)d_out;
        lossdst = (float*)d_out + NC;
    } else if ((long long)out_size == NC) {
        out = (float*)d_out;
    } else {
        cudaGetSymbolAddress((void**)&out, g_out_full);
        lossdst = (float*)d_out + (out_size > 0 ? out_size - 1 : 0);
    }

    cudaFuncSetAttribute(gemm_margin_kernel, cudaFuncAttributeMaxDynamicSharedMemorySize, SMEM_TOTAL);

    norm_rows_kernel<<<N / 8, 256>>>(logits, 0);   // also zeroes g_rowsum
    norm_rows_kernel<<<C / 8, 256>>>(weight, 1);

    // grid.x = M tiles fastest -> 4 blocks sharing a W tile run adjacently (L2 reuse)
    dim3 grid(N / BM, (C + BN - 1) / BN);
    gemm_margin_kernel<<<grid, 128, SMEM_TOTAL>>>(labels, out);

    if (lossdst) {
        finalize_kernel<<<1, N>>>(lossdst);
    }
}

// round 13
// speedup vs baseline: 1.1197x; 1.1197x over previous
#include <cuda_runtime.h>
#include <cuda_fp16.h>
#include <cstdint>
#include <math.h>

// Problem constants
static constexpr int N = 512;      // batch
static constexpr int D = 512;      // features
static constexpr int C = 50000;    // classes
static constexpr float SCALE = 30.0f;
static constexpr float COS_M = 0.8775825618903728f;   // cos(0.5)
static constexpr float SIN_M = 0.479425538604203f;    // sin(0.5)
static constexpr float TH    = -0.8775825618903728f;  // cos(pi-0.5)
static constexpr float MMC   = 0.2397127693021015f;   // sin(pi-0.5)*0.5

// Device scratch (no runtime allocation allowed)
__device__ __half g_xn[(size_t)N * D];       // normalized x, fp16
__device__ __half g_wn[(size_t)C * D];       // normalized W, fp16  (51.2 MB)
__device__ float  g_rowsum[N];               // sum exp(logit - 30) per row
__device__ float  g_picked[N];               // post-margin scaled logit at label
__device__ unsigned int g_done;              // completion counter for fused finalize
// Fallback scratch if out_size < N*C (not expected):
__device__ float  g_out_full[(size_t)N * C];

// ---------------------------------------------------------------------------
__device__ __forceinline__ uint32_t smem_u32(const void* p) {
    uint32_t a;
    asm("{ .reg .u64 t; cvta.to.shared.u64 t, %1; cvt.u32.u64 %0, t; }" : "=r"(a) : "l"(p));
    return a;
}
#define CP_ASYNC16(dst, src) \
    asm volatile("cp.async.cg.shared.global [%0], [%1], 16;" :: "r"(dst), "l"(src) : "memory")
#define CP_ASYNC16_ZF(dst, src, srcsz) \
    asm volatile("cp.async.cg.shared.global [%0], [%1], 16, %2;" :: "r"(dst), "l"(src), "r"(srcsz) : "memory")
#define CP_COMMIT() asm volatile("cp.async.commit_group;" ::: "memory")
#define CP_WAIT(n)  asm volatile("cp.async.wait_group %0;" :: "n"(n) : "memory")

#define LDSM_X4(r0, r1, r2, r3, addr) \
    asm volatile("ldmatrix.sync.aligned.m8n8.x4.shared.b16 {%0,%1,%2,%3}, [%4];" \
        : "=r"(r0), "=r"(r1), "=r"(r2), "=r"(r3) : "r"(addr))

#define MMA16816(d, a, b0_, b1_) \
    asm volatile("mma.sync.aligned.m16n8k16.row.col.f32.f16.f16.f32 " \
        "{%0,%1,%2,%3},{%4,%5,%6,%7},{%8,%9},{%0,%1,%2,%3};" \
        : "+f"((d).x), "+f"((d).y), "+f"((d).z), "+f"((d).w) \
        : "r"((a)[0]), "r"((a)[1]), "r"((a)[2]), "r"((a)[3]), "r"(b0_), "r"(b1_))

// ---------------------------------------------------------------------------
// Row L2-normalize (fp32 in -> fp16 out). Warp per row, 16 rows per block
// (512 threads). which==0 also zeroes g_rowsum and g_done (block 0).
// ---------------------------------------------------------------------------
__global__ void norm_rows_kernel(const float* __restrict__ in, int which)
{
    if (which == 0 && blockIdx.x == 0) {
        g_rowsum[threadIdx.x] = 0.0f;
        if (threadIdx.x == 0) g_done = 0u;
    }
    const int warp = threadIdx.x >> 5;
    const int lane = threadIdx.x & 31;
    const int r = blockIdx.x * 16 + warp;
    const float4* rp = reinterpret_cast<const float4*>(in + (size_t)r * D);
    float4 v[4];
    float ss = 0.0f;
    #pragma unroll
    for (int i = 0; i < 4; i++) {
        v[i] = rp[lane + 32 * i];
        ss += v[i].x * v[i].x + v[i].y * v[i].y + v[i].z * v[i].z + v[i].w * v[i].w;
    }
    #pragma unroll
    for (int o = 16; o; o >>= 1) ss += __shfl_xor_sync(0xFFFFFFFFu, ss, o);
    float inv = 1.0f / fmaxf(sqrtf(ss), 1e-12f);
    __half* dst = which ? g_wn : g_xn;
    __half2* op = reinterpret_cast<__half2*>(dst + (size_t)r * D);
    #pragma unroll
    for (int i = 0; i < 4; i++) {
        op[(lane + 32 * i) * 2 + 0] = __floats2half2_rn(v[i].x * inv, v[i].y * inv);
        op[(lane + 32 * i) * 2 + 1] = __floats2half2_rn(v[i].z * inv, v[i].w * inv);
    }
}

// ---------------------------------------------------------------------------
// GEMM: cosine[N, C] = xn[N, D] * wn[C, D]^T  (fp16 in, fp32 acc)
// Block 128x128, BK=64, 3-stage cp.async pipeline, one sync per K-iter.
// 8 warps (2x4), warp tile 64x32, hand-rolled mma.sync.m16n8k16 + ldmatrix.x4.
// Fused epilogue: phi-margin at label col, x30 scale, per-row exp-sum.
// Last block to finish also computes the mean CE loss (fused finalize).
// ---------------------------------------------------------------------------
static constexpr int BM = 128, BN = 128, BK = 64, BKP = 72;  // 144B rows, ldsm conflict-free
static constexpr int ROWB = BKP * 2;                          // 144 bytes per smem row
static constexpr int A_BYTES = BM * ROWB;                     // 18432
static constexpr int B_BYTES = BN * ROWB;                     // 18432
static constexpr int STAGE_BYTES = A_BYTES + B_BYTES;         // 36864
static constexpr int NSTAGE = 3;
static constexpr int KITERS = D / BK;                         // 8
static constexpr int PIPE_BYTES = NSTAGE * STAGE_BYTES;       // 110592
static constexpr int STG_STRIDE = 132;                        // epilogue stage stride (floats)
static constexpr int ROWSUM_OFF = PIPE_BYTES;
static constexpr int LAB_OFF    = ROWSUM_OFF + 128 * (int)sizeof(float);
static constexpr int SMEM_TOTAL = LAB_OFF + 128 * (int)sizeof(int);   // 111616
static constexpr int GRID_TOTAL = (N / BM) * ((C + BN - 1) / BN);     // 4 * 391 = 1564

__global__ void __launch_bounds__(256, 2)
gemm_margin_kernel(const int* __restrict__ labels, float* __restrict__ out,
                   float* __restrict__ lossdst)
{
    extern __shared__ __align__(16) unsigned char smraw[];
    const uint32_t smb = smem_u32(smraw);
    float* shRow = reinterpret_cast<float*>(smraw + ROWSUM_OFF);
    int*   shLab = reinterpret_cast<int*>(smraw + LAB_OFF);
    float* stage = reinterpret_cast<float*>(smraw);    // epilogue union (128x132 f32 = 67.6KB)

    const int tid  = threadIdx.x;
    const int warp = tid >> 5;
    const int lane = tid & 31;
    const int wRow = warp >> 2;   // 0..1 (64 rows)
    const int wCol = warp & 3;    // 0..3 (32 cols)
    const int rowBase = blockIdx.x * BM;
    const int colBase = blockIdx.y * BN;

    if (tid < 128) {
        shRow[tid] = 0.0f;
        shLab[tid] = labels[rowBase + tid];
    }

    float4 acc[4][4];   // [m16 tile i][n8 tile j]
    #pragma unroll
    for (int i = 0; i < 4; i++)
        #pragma unroll
        for (int j = 0; j < 4; j++)
            acc[i][j] = make_float4(0.f, 0.f, 0.f, 0.f);

    // ldmatrix lane-dependent byte offsets (within a tile's smem region)
    const uint32_t aLane = (uint32_t)((((lane >> 3) & 1) * 8 + (lane & 7)) * ROWB + (lane >> 4) * 16);
    const uint32_t bLane = (uint32_t)(((lane >> 4) * 8 + (lane & 7)) * ROWB + ((lane >> 3) & 1) * 16);
    const uint32_t aWarpBase = (uint32_t)(wRow * 64 * ROWB) + aLane;
    const uint32_t bWarpBase = (uint32_t)(A_BYTES + wCol * 32 * ROWB) + bLane;

    auto prefetch = [&](int kt) {
        const int slot = kt % NSTAGE;
        const uint32_t sA = smb + slot * STAGE_BYTES;
        const uint32_t sB = sA + A_BYTES;
        #pragma unroll
        for (int j = 0; j < 4; j++) {
            int v   = tid + j * 256;
            int row = v >> 3;
            int cv  = v & 7;
            const __half* asrc = g_xn + (size_t)(rowBase + row) * D + kt * BK + cv * 8;
            CP_ASYNC16(sA + (uint32_t)(row * ROWB + cv * 16), asrc);
        }
        #pragma unroll
        for (int j = 0; j < 4; j++) {
            int v   = tid + j * 256;
            int row = v >> 3;
            int cv  = v & 7;
            int cls = colBase + row;
            const __half* bsrc = g_wn + (size_t)cls * D + kt * BK + cv * 8;
            uint32_t sz = (cls < C) ? 16u : 0u;   // zero-fill OOB class rows
            CP_ASYNC16_ZF(sB + (uint32_t)(row * ROWB + cv * 16), bsrc, sz);
        }
        CP_COMMIT();
    };

    prefetch(0);
    prefetch(1);

    for (int kt = 0; kt < KITERS; kt++) {
        if (kt < KITERS - 1) { CP_WAIT(1); } else { CP_WAIT(0); }
        __syncthreads();

        if (kt + 2 < KITERS) prefetch(kt + 2);

        const uint32_t slotBase = smb + (kt % NSTAGE) * STAGE_BYTES;
        const uint32_t aBase = slotBase + aWarpBase;
        const uint32_t bBase = slotBase + bWarpBase;

        #pragma unroll
        for (int ks = 0; ks < BK / 16; ks++) {
            const uint32_t ko = (uint32_t)(ks * 32);
            uint32_t a[4][4];
            #pragma unroll
            for (int i = 0; i < 4; i++)
                LDSM_X4(a[i][0], a[i][1], a[i][2], a[i][3],
                        aBase + (uint32_t)(i * 16 * ROWB) + ko);
            uint32_t b[2][4];
            #pragma unroll
            for (int g = 0; g < 2; g++)
                LDSM_X4(b[g][0], b[g][1], b[g][2], b[g][3],
                        bBase + (uint32_t)(g * 16 * ROWB) + ko);
            #pragma unroll
            for (int i = 0; i < 4; i++) {
                MMA16816(acc[i][0], a[i], b[0][0], b[0][1]);
                MMA16816(acc[i][1], a[i], b[0][2], b[0][3]);
                MMA16816(acc[i][2], a[i], b[1][0], b[1][1]);
                MMA16816(acc[i][3], a[i], b[1][2], b[1][3]);
            }
        }
    }

    // ------------------ fused epilogue -----------------------------------
    __syncthreads();   // mainloop smem reads done; safe to overwrite with stage
    {
        const int gid = lane >> 2;
        const int c2  = (lane & 3) * 2;
        #pragma unroll
        for (int i = 0; i < 4; i++) {
            const int r0 = wRow * 64 + i * 16 + gid;
            #pragma unroll
            for (int j = 0; j < 4; j++) {
                const int col = wCol * 32 + j * 8 + c2;
                *reinterpret_cast<float2*>(stage + r0 * STG_STRIDE + col) =
                    make_float2(acc[i][j].x, acc[i][j].y);
                *reinterpret_cast<float2*>(stage + (r0 + 8) * STG_STRIDE + col) =
                    make_float2(acc[i][j].z, acc[i][j].w);
            }
        }
    }
    __syncthreads();

    // Warp-per-row processing: 8 warps x 16 iters cover 128 rows.
    #pragma unroll 2
    for (int k = 0; k < 16; k++) {
        const int row = warp + k * 8;             // 0..127, warp-uniform
        const int gr  = rowBase + row;
        const int lab = shLab[row];
        const int gc0 = colBase + lane * 4;
        const float* sp = stage + row * STG_STRIDE + lane * 4;
        float4 v = make_float4(sp[0], sp[1], sp[2], sp[3]);
        float e = 0.0f;
        float* vv = &v.x;
        #pragma unroll
        for (int j = 0; j < 4; j++) {
            float cv = vv[j];
            float val;
            if (gc0 + j == lab) {
                float sine = sqrtf(fmaxf(0.0f, fminf(1.0000001f - cv * cv, 1.0f)));
                float ph   = cv * COS_M - sine * SIN_M;
                val = ((cv > TH) ? ph : (cv - MMC)) * SCALE;
                g_picked[gr] = val;
            } else {
                val = cv * SCALE;
            }
            vv[j] = val;
            e += __expf(val - 30.0f);
        }
        if (gc0 < C) {
            *reinterpret_cast<float4*>(out + (size_t)gr * C + gc0) = v;
        } else {
            e = 0.0f;
        }
        #pragma unroll
        for (int o = 16; o; o >>= 1) e += __shfl_xor_sync(0xFFFFFFFFu, e, o);
        if (lane == 0) atomicAdd(&shRow[row], e);
    }
    __syncthreads();
    if (tid < 128) atomicAdd(&g_rowsum[rowBase + tid], shRow[tid]);

    // ------------------ fused finalize (last block) -----------------------
    if (lossdst != nullptr) {
        __shared__ unsigned int sTicket;
        __threadfence();                      // make rowsum/picked writes visible
        __syncthreads();
        if (tid == 0) sTicket = atomicAdd(&g_done, 1u);
        __syncthreads();
        if (sTicket == GRID_TOTAL - 1) {
            // all other blocks' atomics are globally visible now
            float part = 0.0f;
            for (int r = tid; r < N; r += 256) {
                part += (30.0f + logf(g_rowsum[r])) - g_picked[r];
            }
            #pragma unroll
            for (int o = 16; o; o >>= 1) part += __shfl_xor_sync(0xFFFFFFFFu, part, o);
            float* red = stage;               // reuse smem
            if (lane == 0) red[warp] = part;
            __syncthreads();
            if (tid == 0) {
                float tot = 0.0f;
                #pragma unroll
                for (int w = 0; w < 8; w++) tot += red[w];
                lossdst[0] = tot / (float)N;
                g_done = 0u;                  // reset for next (graph) invocation
            }
        }
    }
}

// ---------------------------------------------------------------------------
extern "C" void kernel_launch(void* const* d_in, const int* in_sizes, int n_in,
                              void* d_out, int out_size)
{
    const float* logits = (const float*)d_in[0];  // [512, 512] f32
    const int*   labels = (const int*)  d_in[1];  // [512] int32
    const float* weight = (const float*)d_in[2];  // [50000, 512] f32

    const long long NC = (long long)N * C;
    float* out;
    float* lossdst = nullptr;
    if ((long long)out_size == NC + 1) {
        out = (float*)d_out;
        lossdst = (float*)d_out + NC;
    } else if ((long long)out_size == NC) {
        out = (float*)d_out;
    } else {
        cudaGetSymbolAddress((void**)&out, g_out_full);
        lossdst = (float*)d_out + (out_size > 0 ? out_size - 1 : 0);
    }

    cudaFuncSetAttribute(gemm_margin_kernel, cudaFuncAttributeMaxDynamicSharedMemorySize, SMEM_TOTAL);

    norm_rows_kernel<<<N / 16, 512>>>(logits, 0);   // also zeroes g_rowsum/g_done
    norm_rows_kernel<<<C / 16, 512>>>(weight, 1);

    // grid.x = M tiles fastest -> 4 blocks sharing a W tile run adjacently (L2 reuse)
    dim3 grid(N / BM, (C + BN - 1) / BN);
    gemm_margin_kernel<<<grid, 256, SMEM_TOTAL>>>(labels, out, lossdst);
}

// round 16
// speedup vs baseline: 1.1773x; 1.0515x over previous
#include <cuda_runtime.h>
#include <cuda_fp16.h>
#include <cstdint>
#include <math.h>

// Problem constants
static constexpr int N = 512;      // batch
static constexpr int D = 512;      // features
static constexpr int C = 50000;    // classes
static constexpr float SCALE = 30.0f;
static constexpr float COS_M = 0.8775825618903728f;   // cos(0.5)
static constexpr float SIN_M = 0.479425538604203f;    // sin(0.5)
static constexpr float TH    = -0.8775825618903728f;  // cos(pi-0.5)
static constexpr float MMC   = 0.2397127693021015f;   // sin(pi-0.5)*0.5

// Device scratch (no runtime allocation allowed)
__device__ __half g_xn[(size_t)N * D];       // normalized x, fp16
__device__ __half g_wn[(size_t)C * D];       // normalized W, fp16  (51.2 MB)
__device__ float  g_rowsum[N];               // sum exp(logit - 30) per row
__device__ float  g_picked[N];               // post-margin scaled logit at label
// Fallback scratch if out_size < N*C (not expected):
__device__ float  g_out_full[(size_t)N * C];

// ---------------------------------------------------------------------------
__device__ __forceinline__ uint32_t smem_u32(const void* p) {
    uint32_t a;
    asm("{ .reg .u64 t; cvta.to.shared.u64 t, %1; cvt.u32.u64 %0, t; }" : "=r"(a) : "l"(p));
    return a;
}
#define CP_ASYNC16(dst, src) \
    asm volatile("cp.async.cg.shared.global [%0], [%1], 16;" :: "r"(dst), "l"(src) : "memory")
#define CP_ASYNC16_ZF(dst, src, srcsz) \
    asm volatile("cp.async.cg.shared.global [%0], [%1], 16, %2;" :: "r"(dst), "l"(src), "r"(srcsz) : "memory")
#define CP_COMMIT() asm volatile("cp.async.commit_group;" ::: "memory")
#define CP_WAIT(n)  asm volatile("cp.async.wait_group %0;" :: "n"(n) : "memory")

#define LDSM_X4(r0, r1, r2, r3, addr) \
    asm volatile("ldmatrix.sync.aligned.m8n8.x4.shared.b16 {%0,%1,%2,%3}, [%4];" \
        : "=r"(r0), "=r"(r1), "=r"(r2), "=r"(r3) : "r"(addr))

#define MMA16816(d, a, b0_, b1_) \
    asm volatile("mma.sync.aligned.m16n8k16.row.col.f32.f16.f16.f32 " \
        "{%0,%1,%2,%3},{%4,%5,%6,%7},{%8,%9},{%0,%1,%2,%3};" \
        : "+f"((d).x), "+f"((d).y), "+f"((d).z), "+f"((d).w) \
        : "r"((a)[0]), "r"((a)[1]), "r"((a)[2]), "r"((a)[3]), "r"(b0_), "r"(b1_))

// ---------------------------------------------------------------------------
// Row L2-normalize (fp32 in -> fp16 out), BOTH tensors in one launch.
// Warp per row, 16 rows per block (512 threads).
// Blocks [0, XB)       -> x rows      (block 0 also zeroes g_rowsum)
// Blocks [XB, XB+WB)   -> W rows
// ---------------------------------------------------------------------------
static constexpr int XB = N / 16;        // 32
static constexpr int WB = C / 16;        // 3125

__global__ void norm_rows_kernel(const float* __restrict__ x, const float* __restrict__ w)
{
    const bool isX = (blockIdx.x < XB);
    if (blockIdx.x == 0) g_rowsum[threadIdx.x] = 0.0f;
    const int warp = threadIdx.x >> 5;
    const int lane = threadIdx.x & 31;
    const int r = (isX ? blockIdx.x : blockIdx.x - XB) * 16 + warp;
    const float* in = isX ? x : w;
    const float4* rp = reinterpret_cast<const float4*>(in + (size_t)r * D);
    float4 v[4];
    float ss = 0.0f;
    #pragma unroll
    for (int i = 0; i < 4; i++) {
        v[i] = rp[lane + 32 * i];
        ss += v[i].x * v[i].x + v[i].y * v[i].y + v[i].z * v[i].z + v[i].w * v[i].w;
    }
    #pragma unroll
    for (int o = 16; o; o >>= 1) ss += __shfl_xor_sync(0xFFFFFFFFu, ss, o);
    float inv = 1.0f / fmaxf(sqrtf(ss), 1e-12f);
    __half* dst = isX ? g_xn : g_wn;
    __half2* op = reinterpret_cast<__half2*>(dst + (size_t)r * D);
    #pragma unroll
    for (int i = 0; i < 4; i++) {
        op[(lane + 32 * i) * 2 + 0] = __floats2half2_rn(v[i].x * inv, v[i].y * inv);
        op[(lane + 32 * i) * 2 + 1] = __floats2half2_rn(v[i].z * inv, v[i].w * inv);
    }
}

// ---------------------------------------------------------------------------
// GEMM: cosine[N, C] = xn[N, D] * wn[C, D]^T  (fp16 in, fp32 acc)
// Block 128x128, BK=64, 3-stage cp.async pipeline.
// Per K-iter: CP_WAIT(own groups) -> __syncthreads (publish) -> prefetch -> MMA.
// 8 warps (2x4), warp tile 64x32, hand-rolled mma.sync.m16n8k16 + ldmatrix.x4.
// Fused epilogue: phi-margin at label col, x30 scale, per-row exp-sum.
// ---------------------------------------------------------------------------
static constexpr int BM = 128, BN = 128, BK = 64, BKP = 72;  // 144B rows, ldsm conflict-free
static constexpr int ROWB = BKP * 2;                          // 144 bytes per smem row
static constexpr int A_BYTES = BM * ROWB;                     // 18432
static constexpr int B_BYTES = BN * ROWB;                     // 18432
static constexpr int STAGE_BYTES = A_BYTES + B_BYTES;         // 36864
static constexpr int NSTAGE = 3;
static constexpr int KITERS = D / BK;                         // 8
static constexpr int PIPE_BYTES = NSTAGE * STAGE_BYTES;       // 110592
static constexpr int STG_STRIDE = 132;                        // epilogue stage stride (floats)
static constexpr int ROWSUM_OFF = PIPE_BYTES;
static constexpr int LAB_OFF    = ROWSUM_OFF + 128 * (int)sizeof(float);
static constexpr int SMEM_TOTAL = LAB_OFF + 128 * (int)sizeof(int);   // 111616

__global__ void __launch_bounds__(256, 2)
gemm_margin_kernel(const int* __restrict__ labels, float* __restrict__ out)
{
    extern __shared__ __align__(16) unsigned char smraw[];
    const uint32_t smb = smem_u32(smraw);
    float* shRow = reinterpret_cast<float*>(smraw + ROWSUM_OFF);
    int*   shLab = reinterpret_cast<int*>(smraw + LAB_OFF);
    float* stage = reinterpret_cast<float*>(smraw);    // epilogue union (128x132 f32 = 67.6KB)

    const int tid  = threadIdx.x;
    const int warp = tid >> 5;
    const int lane = tid & 31;
    const int wRow = warp >> 2;   // 0..1 (64 rows)
    const int wCol = warp & 3;    // 0..3 (32 cols)
    const int rowBase = blockIdx.x * BM;
    const int colBase = blockIdx.y * BN;

    if (tid < 128) {
        shRow[tid] = 0.0f;
        shLab[tid] = labels[rowBase + tid];
    }

    float4 acc[4][4];   // [m16 tile i][n8 tile j]
    #pragma unroll
    for (int i = 0; i < 4; i++)
        #pragma unroll
        for (int j = 0; j < 4; j++)
            acc[i][j] = make_float4(0.f, 0.f, 0.f, 0.f);

    // ldmatrix lane-dependent byte offsets (within a tile's smem region)
    const uint32_t aLane = (uint32_t)((((lane >> 3) & 1) * 8 + (lane & 7)) * ROWB + (lane >> 4) * 16);
    const uint32_t bLane = (uint32_t)(((lane >> 4) * 8 + (lane & 7)) * ROWB + ((lane >> 3) & 1) * 16);
    const uint32_t aWarpBase = (uint32_t)(wRow * 64 * ROWB) + aLane;
    const uint32_t bWarpBase = (uint32_t)(A_BYTES + wCol * 32 * ROWB) + bLane;

    auto prefetch = [&](int kt) {
        const int slot = kt % NSTAGE;
        const uint32_t sA = smb + slot * STAGE_BYTES;
        const uint32_t sB = sA + A_BYTES;
        #pragma unroll
        for (int j = 0; j < 4; j++) {
            int v   = tid + j * 256;
            int row = v >> 3;
            int cv  = v & 7;
            const __half* asrc = g_xn + (size_t)(rowBase + row) * D + kt * BK + cv * 8;
            CP_ASYNC16(sA + (uint32_t)(row * ROWB + cv * 16), asrc);
        }
        #pragma unroll
        for (int j = 0; j < 4; j++) {
            int v   = tid + j * 256;
            int row = v >> 3;
            int cv  = v & 7;
            int cls = colBase + row;
            const __half* bsrc = g_wn + (size_t)cls * D + kt * BK + cv * 8;
            uint32_t sz = (cls < C) ? 16u : 0u;   // zero-fill OOB class rows
            CP_ASYNC16_ZF(sB + (uint32_t)(row * ROWB + cv * 16), bsrc, sz);
        }
        CP_COMMIT();
    };

    prefetch(0);
    prefetch(1);

    for (int kt = 0; kt < KITERS; kt++) {
        // CORRECT cp.async protocol: each thread waits for its OWN groups,
        // then the barrier publishes all threads' copies to the block.
        if (kt < KITERS - 1) { CP_WAIT(1); } else { CP_WAIT(0); }
        __syncthreads();

        if (kt + 2 < KITERS) prefetch(kt + 2);

        const uint32_t slotBase = smb + (kt % NSTAGE) * STAGE_BYTES;
        const uint32_t aBase = slotBase + aWarpBase;
        const uint32_t bBase = slotBase + bWarpBase;

        #pragma unroll
        for (int ks = 0; ks < BK / 16; ks++) {
            const uint32_t ko = (uint32_t)(ks * 32);
            uint32_t a[4][4];
            #pragma unroll
            for (int i = 0; i < 4; i++)
                LDSM_X4(a[i][0], a[i][1], a[i][2], a[i][3],
                        aBase + (uint32_t)(i * 16 * ROWB) + ko);
            uint32_t b[2][4];
            #pragma unroll
            for (int g = 0; g < 2; g++)
                LDSM_X4(b[g][0], b[g][1], b[g][2], b[g][3],
                        bBase + (uint32_t)(g * 16 * ROWB) + ko);
            #pragma unroll
            for (int i = 0; i < 4; i++) {
                MMA16816(acc[i][0], a[i], b[0][0], b[0][1]);
                MMA16816(acc[i][1], a[i], b[0][2], b[0][3]);
                MMA16816(acc[i][2], a[i], b[1][0], b[1][1]);
                MMA16816(acc[i][3], a[i], b[1][2], b[1][3]);
            }
        }
    }

    // ------------------ fused epilogue -----------------------------------
    __syncthreads();   // mainloop smem reads done; safe to overwrite with stage
    {
        const int gid = lane >> 2;
        const int c2  = (lane & 3) * 2;
        #pragma unroll
        for (int i = 0; i < 4; i++) {
            const int r0 = wRow * 64 + i * 16 + gid;
            #pragma unroll
            for (int j = 0; j < 4; j++) {
                const int col = wCol * 32 + j * 8 + c2;
                *reinterpret_cast<float2*>(stage + r0 * STG_STRIDE + col) =
                    make_float2(acc[i][j].x, acc[i][j].y);
                *reinterpret_cast<float2*>(stage + (r0 + 8) * STG_STRIDE + col) =
                    make_float2(acc[i][j].z, acc[i][j].w);
            }
        }
    }
    __syncthreads();

    // Warp-per-row processing: 8 warps x 16 iters cover 128 rows.
    #pragma unroll 2
    for (int k = 0; k < 16; k++) {
        const int row = warp + k * 8;             // 0..127, warp-uniform
        const int gr  = rowBase + row;
        const int lab = shLab[row];
        const int gc0 = colBase + lane * 4;
        const float* sp = stage + row * STG_STRIDE + lane * 4;
        float4 v = make_float4(sp[0], sp[1], sp[2], sp[3]);
        float e = 0.0f;
        float* vv = &v.x;
        #pragma unroll
        for (int j = 0; j < 4; j++) {
            float cv = vv[j];
            float val;
            if (gc0 + j == lab) {
                float sine = sqrtf(fmaxf(0.0f, fminf(1.0000001f - cv * cv, 1.0f)));
                float ph   = cv * COS_M - sine * SIN_M;
                val = ((cv > TH) ? ph : (cv - MMC)) * SCALE;
                g_picked[gr] = val;
            } else {
                val = cv * SCALE;
            }
            vv[j] = val;
            e += __expf(val - 30.0f);
        }
        if (gc0 < C) {
            *reinterpret_cast<float4*>(out + (size_t)gr * C + gc0) = v;
        } else {
            e = 0.0f;
        }
        #pragma unroll
        for (int o = 16; o; o >>= 1) e += __shfl_xor_sync(0xFFFFFFFFu, e, o);
        if (lane == 0) atomicAdd(&shRow[row], e);
    }
    __syncthreads();
    if (tid < 128) atomicAdd(&g_rowsum[rowBase + tid], shRow[tid]);
}

// ---------------------------------------------------------------------------
// Final loss: lse_r = 30 + log(rowsum_r); loss = mean(lse - picked)
// ---------------------------------------------------------------------------
__global__ void finalize_kernel(float* __restrict__ dst)
{
    int tid = threadIdx.x;   // 512 threads
    float v = (30.0f + logf(g_rowsum[tid])) - g_picked[tid];
    #pragma unroll
    for (int o = 16; o; o >>= 1) v += __shfl_xor_sync(0xFFFFFFFFu, v, o);
    __shared__ float sh[16];
    if ((tid & 31) == 0) sh[tid >> 5] = v;
    __syncthreads();
    if (tid == 0) {
        float tot = 0.0f;
        #pragma unroll
        for (int w = 0; w < 16; w++) tot += sh[w];
        dst[0] = tot / (float)N;
    }
}

// ---------------------------------------------------------------------------
extern "C" void kernel_launch(void* const* d_in, const int* in_sizes, int n_in,
                              void* d_out, int out_size)
{
    const float* logits = (const float*)d_in[0];  // [512, 512] f32
    const int*   labels = (const int*)  d_in[1];  // [512] int32
    const float* weight = (const float*)d_in[2];  // [50000, 512] f32

    const long long NC = (long long)N * C;
    float* out;
    float* lossdst = nullptr;
    if ((long long)out_size == NC + 1) {
        out = (float*)d_out;
        lossdst = (float*)d_out + NC;
    } else if ((long long)out_size == NC) {
        out = (float*)d_out;
    } else {
        cudaGetSymbolAddress((void**)&out, g_out_full);
        lossdst = (float*)d_out + (out_size > 0 ? out_size - 1 : 0);
    }

    cudaFuncSetAttribute(gemm_margin_kernel, cudaFuncAttributeMaxDynamicSharedMemorySize, SMEM_TOTAL);

    // One launch normalizes x AND W (x blocks overlap the big W wave)
    norm_rows_kernel<<<XB + WB, 512>>>(logits, weight);

    // grid.x = M tiles fastest -> 4 blocks sharing a W tile run adjacently (L2 reuse)
    dim3 grid(N / BM, (C + BN - 1) / BN);
    gemm_margin_kernel<<<grid, 256, SMEM_TOTAL>>>(labels, out);

    if (lossdst) {
        finalize_kernel<<<1, N>>>(lossdst);
    }
}

// round 17
// speedup vs baseline: 1.3398x; 1.1380x over previous
#include <cuda_runtime.h>
#include <cuda_fp16.h>
#include <cstdint>
#include <math.h>

// Problem constants
static constexpr int N = 512;      // batch
static constexpr int D = 512;      // features
static constexpr int C = 50000;    // classes
static constexpr float SCALE = 30.0f;
static constexpr float COS_M = 0.8775825618903728f;   // cos(0.5)
static constexpr float SIN_M = 0.479425538604203f;    // sin(0.5)
static constexpr float TH    = -0.8775825618903728f;  // cos(pi-0.5)
static constexpr float MMC   = 0.2397127693021015f;   // sin(pi-0.5)*0.5

// Device scratch (no runtime allocation allowed)
__device__ __half g_xn[(size_t)N * D];       // normalized x, fp16
__device__ __half g_wn[(size_t)C * D];       // normalized W, fp16  (51.2 MB)
__device__ float  g_rowsum[N];               // sum exp(logit - 30) per row
__device__ float  g_picked[N];               // post-margin scaled logit at label
// Fallback scratch if out_size < N*C (not expected):
__device__ float  g_out_full[(size_t)N * C];

// ---------------------------------------------------------------------------
__device__ __forceinline__ uint32_t smem_u32(const void* p) {
    uint32_t a;
    asm("{ .reg .u64 t; cvta.to.shared.u64 t, %1; cvt.u32.u64 %0, t; }" : "=r"(a) : "l"(p));
    return a;
}
#define CP_ASYNC16(dst, src) \
    asm volatile("cp.async.cg.shared.global [%0], [%1], 16;" :: "r"(dst), "l"(src) : "memory")
#define CP_ASYNC16_ZF(dst, src, srcsz) \
    asm volatile("cp.async.cg.shared.global [%0], [%1], 16, %2;" :: "r"(dst), "l"(src), "r"(srcsz) : "memory")
#define CP_COMMIT() asm volatile("cp.async.commit_group;" ::: "memory")
#define CP_WAIT(n)  asm volatile("cp.async.wait_group %0;" :: "n"(n) : "memory")

#define LDSM_X4(r0, r1, r2, r3, addr) \
    asm volatile("ldmatrix.sync.aligned.m8n8.x4.shared.b16 {%0,%1,%2,%3}, [%4];" \
        : "=r"(r0), "=r"(r1), "=r"(r2), "=r"(r3) : "r"(addr))

#define MMA16816(d, a, b0_, b1_) \
    asm volatile("mma.sync.aligned.m16n8k16.row.col.f32.f16.f16.f32 " \
        "{%0,%1,%2,%3},{%4,%5,%6,%7},{%8,%9},{%0,%1,%2,%3};" \
        : "+f"((d).x), "+f"((d).y), "+f"((d).z), "+f"((d).w) \
        : "r"((a)[0]), "r"((a)[1]), "r"((a)[2]), "r"((a)[3]), "r"(b0_), "r"(b1_))

#define STG_CS_V2(ptr, a_, b_) \
    asm volatile("st.global.cs.v2.f32 [%0], {%1,%2};" :: "l"(ptr), "f"(a_), "f"(b_) : "memory")

// ---------------------------------------------------------------------------
// Row L2-normalize (fp32 in -> fp16 out), BOTH tensors in one launch.
// Warp per row, 16 rows per block (512 threads).
// Blocks [0, XB)       -> x rows      (block 0 also zeroes g_rowsum)
// Blocks [XB, XB+WB)   -> W rows
// ---------------------------------------------------------------------------
static constexpr int XB = N / 16;        // 32
static constexpr int WB = C / 16;        // 3125

__global__ void norm_rows_kernel(const float* __restrict__ x, const float* __restrict__ w)
{
    const bool isX = (blockIdx.x < XB);
    if (blockIdx.x == 0) g_rowsum[threadIdx.x] = 0.0f;
    const int warp = threadIdx.x >> 5;
    const int lane = threadIdx.x & 31;
    const int r = (isX ? blockIdx.x : blockIdx.x - XB) * 16 + warp;
    const float* in = isX ? x : w;
    const float4* rp = reinterpret_cast<const float4*>(in + (size_t)r * D);
    float4 v[4];
    float ss = 0.0f;
    #pragma unroll
    for (int i = 0; i < 4; i++) {
        v[i] = rp[lane + 32 * i];
        ss += v[i].x * v[i].x + v[i].y * v[i].y + v[i].z * v[i].z + v[i].w * v[i].w;
    }
    #pragma unroll
    for (int o = 16; o; o >>= 1) ss += __shfl_xor_sync(0xFFFFFFFFu, ss, o);
    float inv = 1.0f / fmaxf(sqrtf(ss), 1e-12f);
    __half* dst = isX ? g_xn : g_wn;
    __half2* op = reinterpret_cast<__half2*>(dst + (size_t)r * D);
    #pragma unroll
    for (int i = 0; i < 4; i++) {
        op[(lane + 32 * i) * 2 + 0] = __floats2half2_rn(v[i].x * inv, v[i].y * inv);
        op[(lane + 32 * i) * 2 + 1] = __floats2half2_rn(v[i].z * inv, v[i].w * inv);
    }
}

// ---------------------------------------------------------------------------
// GEMM: cosine[N, C] = xn[N, D] * wn[C, D]^T  (fp16 in, fp32 acc)
// Block 128x128, BK=64, 3-stage cp.async pipeline.
// Per K-iter: CP_WAIT(own groups) -> __syncthreads (publish) -> prefetch -> MMA.
// 8 warps (2x4), warp tile 64x32, hand-rolled mma.sync.m16n8k16 + ldmatrix.x4.
// Epilogue DIRECT from registers: margin at label col, x30 scale, per-row
// exp-sum via quad-shfl + shared atomics, st.global.cs.v2 stores (no smem
// staging round-trip, no extra barriers, no L2 pollution from output).
// ---------------------------------------------------------------------------
static constexpr int BM = 128, BN = 128, BK = 64, BKP = 72;  // 144B rows, ldsm conflict-free
static constexpr int ROWB = BKP * 2;                          // 144 bytes per smem row
static constexpr int A_BYTES = BM * ROWB;                     // 18432
static constexpr int B_BYTES = BN * ROWB;                     // 18432
static constexpr int STAGE_BYTES = A_BYTES + B_BYTES;         // 36864
static constexpr int NSTAGE = 3;
static constexpr int KITERS = D / BK;                         // 8
static constexpr int PIPE_BYTES = NSTAGE * STAGE_BYTES;       // 110592
static constexpr int ROWSUM_OFF = PIPE_BYTES;
static constexpr int LAB_OFF    = ROWSUM_OFF + 128 * (int)sizeof(float);
static constexpr int SMEM_TOTAL = LAB_OFF + 128 * (int)sizeof(int);   // 111616

__global__ void __launch_bounds__(256, 2)
gemm_margin_kernel(const int* __restrict__ labels, float* __restrict__ out)
{
    extern __shared__ __align__(16) unsigned char smraw[];
    const uint32_t smb = smem_u32(smraw);
    float* shRow = reinterpret_cast<float*>(smraw + ROWSUM_OFF);
    int*   shLab = reinterpret_cast<int*>(smraw + LAB_OFF);

    const int tid  = threadIdx.x;
    const int warp = tid >> 5;
    const int lane = tid & 31;
    const int wRow = warp >> 2;   // 0..1 (64 rows)
    const int wCol = warp & 3;    // 0..3 (32 cols)
    const int rowBase = blockIdx.x * BM;
    const int colBase = blockIdx.y * BN;

    if (tid < 128) {
        shRow[tid] = 0.0f;
        shLab[tid] = labels[rowBase + tid];
    }

    float4 acc[4][4];   // [m16 tile i][n8 tile j]
    #pragma unroll
    for (int i = 0; i < 4; i++)
        #pragma unroll
        for (int j = 0; j < 4; j++)
            acc[i][j] = make_float4(0.f, 0.f, 0.f, 0.f);

    // ldmatrix lane-dependent byte offsets (within a tile's smem region)
    const uint32_t aLane = (uint32_t)((((lane >> 3) & 1) * 8 + (lane & 7)) * ROWB + (lane >> 4) * 16);
    const uint32_t bLane = (uint32_t)(((lane >> 4) * 8 + (lane & 7)) * ROWB + ((lane >> 3) & 1) * 16);
    const uint32_t aWarpBase = (uint32_t)(wRow * 64 * ROWB) + aLane;
    const uint32_t bWarpBase = (uint32_t)(A_BYTES + wCol * 32 * ROWB) + bLane;

    auto prefetch = [&](int kt) {
        const int slot = kt % NSTAGE;
        const uint32_t sA = smb + slot * STAGE_BYTES;
        const uint32_t sB = sA + A_BYTES;
        #pragma unroll
        for (int j = 0; j < 4; j++) {
            int v   = tid + j * 256;
            int row = v >> 3;
            int cv  = v & 7;
            const __half* asrc = g_xn + (size_t)(rowBase + row) * D + kt * BK + cv * 8;
            CP_ASYNC16(sA + (uint32_t)(row * ROWB + cv * 16), asrc);
        }
        #pragma unroll
        for (int j = 0; j < 4; j++) {
            int v   = tid + j * 256;
            int row = v >> 3;
            int cv  = v & 7;
            int cls = colBase + row;
            const __half* bsrc = g_wn + (size_t)cls * D + kt * BK + cv * 8;
            uint32_t sz = (cls < C) ? 16u : 0u;   // zero-fill OOB class rows
            CP_ASYNC16_ZF(sB + (uint32_t)(row * ROWB + cv * 16), bsrc, sz);
        }
        CP_COMMIT();
    };

    prefetch(0);
    prefetch(1);

    for (int kt = 0; kt < KITERS; kt++) {
        // cp.async protocol: each thread waits for its OWN groups, then the
        // barrier publishes all threads' copies to the block.
        if (kt < KITERS - 1) { CP_WAIT(1); } else { CP_WAIT(0); }
        __syncthreads();

        if (kt + 2 < KITERS) prefetch(kt + 2);

        const uint32_t slotBase = smb + (kt % NSTAGE) * STAGE_BYTES;
        const uint32_t aBase = slotBase + aWarpBase;
        const uint32_t bBase = slotBase + bWarpBase;

        #pragma unroll
        for (int ks = 0; ks < BK / 16; ks++) {
            const uint32_t ko = (uint32_t)(ks * 32);
            uint32_t a[4][4];
            #pragma unroll
            for (int i = 0; i < 4; i++)
                LDSM_X4(a[i][0], a[i][1], a[i][2], a[i][3],
                        aBase + (uint32_t)(i * 16 * ROWB) + ko);
            uint32_t b[2][4];
            #pragma unroll
            for (int g = 0; g < 2; g++)
                LDSM_X4(b[g][0], b[g][1], b[g][2], b[g][3],
                        bBase + (uint32_t)(g * 16 * ROWB) + ko);
            #pragma unroll
            for (int i = 0; i < 4; i++) {
                MMA16816(acc[i][0], a[i], b[0][0], b[0][1]);
                MMA16816(acc[i][1], a[i], b[0][2], b[0][3]);
                MMA16816(acc[i][2], a[i], b[1][0], b[1][1]);
                MMA16816(acc[i][3], a[i], b[1][2], b[1][3]);
            }
        }
    }

    // ------------- direct-from-register fused epilogue --------------------
    // Fragment layout: thread quad q=lane>>2 owns rows (i*16+q, +8); lane&3
    // selects col pair. Per (i,j): acc.x,.y -> row0 cols (gc,gc+1);
    // acc.z,.w -> row1. Quad's 4 lanes cover 8 consecutive cols = one 32B
    // sector, so direct v2 stores are sector-dense. No smem staging needed.
    {
        const int gid = lane >> 2;
        const int c2  = (lane & 3) * 2;

        #pragma unroll
        for (int i = 0; i < 4; i++) {
            const int lr0 = wRow * 64 + i * 16 + gid;
            const int lr1 = lr0 + 8;
            const int gr0 = rowBase + lr0;
            const int gr1 = rowBase + lr1;
            const int lab0 = shLab[lr0];
            const int lab1 = shLab[lr1];
            float e0 = 0.0f, e1 = 0.0f;
            #pragma unroll
            for (int j = 0; j < 4; j++) {
                const int gc = colBase + wCol * 32 + j * 8 + c2;
                float p[4] = { acc[i][j].x, acc[i][j].y, acc[i][j].z, acc[i][j].w };
                // rows: p[0],p[1] -> gr0 ; p[2],p[3] -> gr1
                #pragma unroll
                for (int h = 0; h < 4; h++) {
                    const int col = gc + (h & 1);
                    const int lab = (h < 2) ? lab0 : lab1;
                    const int gr  = (h < 2) ? gr0 : gr1;
                    float cv = p[h];
                    float val;
                    if (col == lab) {
                        float sine = sqrtf(fmaxf(0.0f, fminf(1.0000001f - cv * cv, 1.0f)));
                        float ph   = cv * COS_M - sine * SIN_M;
                        val = ((cv > TH) ? ph : (cv - MMC)) * SCALE;
                        g_picked[gr] = val;
                    } else {
                        val = cv * SCALE;
                    }
                    p[h] = val;
                }
                if (gc < C) {   // C even, gc even -> pair fully in-bounds
                    e0 += __expf(p[0] - 30.0f) + __expf(p[1] - 30.0f);
                    e1 += __expf(p[2] - 30.0f) + __expf(p[3] - 30.0f);
                    STG_CS_V2(out + (size_t)gr0 * C + gc, p[0], p[1]);
                    STG_CS_V2(out + (size_t)gr1 * C + gc, p[2], p[3]);
                }
            }
            // quad-level reduction (lanes differ only in col pair)
            e0 += __shfl_xor_sync(0xFFFFFFFFu, e0, 1);
            e0 += __shfl_xor_sync(0xFFFFFFFFu, e0, 2);
            e1 += __shfl_xor_sync(0xFFFFFFFFu, e1, 1);
            e1 += __shfl_xor_sync(0xFFFFFFFFu, e1, 2);
            if ((lane & 3) == 0) {
                atomicAdd(&shRow[lr0], e0);
                atomicAdd(&shRow[lr1], e1);
            }
        }
    }
    __syncthreads();
    if (tid < 128) atomicAdd(&g_rowsum[rowBase + tid], shRow[tid]);
}

// ---------------------------------------------------------------------------
// Final loss: lse_r = 30 + log(rowsum_r); loss = mean(lse - picked)
// ---------------------------------------------------------------------------
__global__ void finalize_kernel(float* __restrict__ dst)
{
    int tid = threadIdx.x;   // 512 threads
    float v = (30.0f + logf(g_rowsum[tid])) - g_picked[tid];
    #pragma unroll
    for (int o = 16; o; o >>= 1) v += __shfl_xor_sync(0xFFFFFFFFu, v, o);
    __shared__ float sh[16];
    if ((tid & 31) == 0) sh[tid >> 5] = v;
    __syncthreads();
    if (tid == 0) {
        float tot = 0.0f;
        #pragma unroll
        for (int w = 0; w < 16; w++) tot += sh[w];
        dst[0] = tot / (float)N;
    }
}

// ---------------------------------------------------------------------------
extern "C" void kernel_launch(void* const* d_in, const int* in_sizes, int n_in,
                              void* d_out, int out_size)
{
    const float* logits = (const float*)d_in[0];  // [512, 512] f32
    const int*   labels = (const int*)  d_in[1];  // [512] int32
    const float* weight = (const float*)d_in[2];  // [50000, 512] f32

    const long long NC = (long long)N * C;
    float* out;
    float* lossdst = nullptr;
    if ((long long)out_size == NC + 1) {
        out = (float*)d_out;
        lossdst = (float*)d_out + NC;
    } else if ((long long)out_size == NC) {
        out = (float*)d_out;
    } else {
        cudaGetSymbolAddress((void**)&out, g_out_full);
        lossdst = (float*)d_out + (out_size > 0 ? out_size - 1 : 0);
    }

    cudaFuncSetAttribute(gemm_margin_kernel, cudaFuncAttributeMaxDynamicSharedMemorySize, SMEM_TOTAL);

    // One launch normalizes x AND W (x blocks overlap the big W wave)
    norm_rows_kernel<<<XB + WB, 512>>>(logits, weight);

    // grid.x = M tiles fastest -> 4 blocks sharing a W tile run adjacently (L2 reuse)
    dim3 grid(N / BM, (C + BN - 1) / BN);
    gemm_margin_kernel<<<grid, 256, SMEM_TOTAL>>>(labels, out);

    if (lossdst) {
        finalize_kernel<<<1, N>>>(lossdst);
    }
}